// round 7
// baseline (speedup 1.0000x reference)
#include <cuda_runtime.h>
#include <cuda_bf16.h>
#include <cstdint>

#define DIM 256
#define NQ  8192
#define NE  8192
#define KS  512            // physical split K = [hi 256 | lo 256]
#define ZQ_ELEMS (NQ * DIM)
#define NSTRIP 16          // N blocks (512 codes each)
#define NCHUNK 6           // logical k-chunks per sub-tile (K=768)

// smem: A 128x(512 pad) bf16 = 133,120 B; B 2 x 128x(128 pad 136) bf16
#define A_ROW_U 65                       // 16B units per A row (64 + 1 pad)
#define B_ROW_U 17                       // 16B units per B row (16 + 1 pad)
#define A_BYTES (128 * A_ROW_U * 16)     // 133120
#define B_BYTES (128 * B_ROW_U * 16)     // 34816
#define SMEM_MM (A_BYTES + 2 * B_BYTES)  // 202752

// ---------------- device scratch ----------------
__device__ float g_znorm[NQ * DIM];
__device__ float g_znorm2[NQ];
__device__ float g_enorm[NE * DIM];
__device__ float g_enorm2[NE];
__device__ __nv_bfloat16 g_zsplit[NQ * KS];
__device__ __nv_bfloat16 g_esplit[NE * KS];
__device__ float g_part_best[NSTRIP * NQ];
__device__ float g_part_2nd [NSTRIP * NQ];
__device__ int   g_part_idx [NSTRIP * NQ];
__device__ int   g_idx[NQ];
__device__ int   g_flag[NQ];
__device__ float g_partial[1024];

// ---------------- PTX helpers (sm_80-era, base-target safe) ----------------
__device__ __forceinline__ uint32_t smem_u32(const void* p) {
    uint32_t a;
    asm("{ .reg .u64 t; cvta.to.shared.u64 t, %1; cvt.u32.u64 %0, t; }" : "=r"(a) : "l"(p));
    return a;
}
__device__ __forceinline__ void cp16(uint32_t dst, const void* src) {
    asm volatile("cp.async.cg.shared.global [%0], [%1], 16;" :: "r"(dst), "l"(src));
}
__device__ __forceinline__ void cp_commit() {
    asm volatile("cp.async.commit_group;");
}
template <int N>
__device__ __forceinline__ void cp_wait() {
    asm volatile("cp.async.wait_group %0;" :: "n"(N));
}
__device__ __forceinline__ void ldsm4(uint32_t& r0, uint32_t& r1, uint32_t& r2,
                                      uint32_t& r3, uint32_t addr) {
    asm volatile("ldmatrix.sync.aligned.m8n8.x4.shared.b16 {%0,%1,%2,%3}, [%4];"
                 : "=r"(r0), "=r"(r1), "=r"(r2), "=r"(r3) : "r"(addr));
}
__device__ __forceinline__ void mma16816(float* c, uint32_t a0, uint32_t a1,
                                         uint32_t a2, uint32_t a3,
                                         uint32_t b0, uint32_t b1) {
    asm volatile(
        "mma.sync.aligned.m16n8k16.row.col.f32.bf16.bf16.f32 "
        "{%0,%1,%2,%3}, {%4,%5,%6,%7}, {%8,%9}, {%0,%1,%2,%3};"
        : "+f"(c[0]), "+f"(c[1]), "+f"(c[2]), "+f"(c[3])
        : "r"(a0), "r"(a1), "r"(a2), "r"(a3), "r"(b0), "r"(b1));
}

// ---------------- L2 normalize + bf16 hi/lo split ----------------
__global__ void l2norm_rows(const float* __restrict__ in, int rows, int is_code) {
    int warp = (blockIdx.x * blockDim.x + threadIdx.x) >> 5;
    int lane = threadIdx.x & 31;
    if (warp >= rows) return;
    float* __restrict__ out = is_code ? g_enorm : g_znorm;
    __nv_bfloat16* __restrict__ sp = is_code ? g_esplit : g_zsplit;
    const float4* src = (const float4*)(in + (size_t)warp * DIM);
    float4 v0 = src[lane];
    float4 v1 = src[lane + 32];
    float s = v0.x*v0.x + v0.y*v0.y + v0.z*v0.z + v0.w*v0.w
            + v1.x*v1.x + v1.y*v1.y + v1.z*v1.z + v1.w*v1.w;
    #pragma unroll
    for (int off = 16; off; off >>= 1) s += __shfl_xor_sync(0xffffffffu, s, off);
    float inv = 1.0f / fmaxf(sqrtf(s), 1e-12f);
    v0.x *= inv; v0.y *= inv; v0.z *= inv; v0.w *= inv;
    v1.x *= inv; v1.y *= inv; v1.z *= inv; v1.w *= inv;
    float4* dst = (float4*)(out + (size_t)warp * DIM);
    dst[lane]      = v0;
    dst[lane + 32] = v1;
    size_t base = (size_t)warp * KS;
    float vals[8] = {v0.x, v0.y, v0.z, v0.w, v1.x, v1.y, v1.z, v1.w};
    #pragma unroll
    for (int j = 0; j < 8; j++) {
        int k = (j < 4) ? (4 * lane + j) : (128 + 4 * lane + (j - 4));
        __nv_bfloat16 h = __float2bfloat16(vals[j]);
        float hf = __bfloat162float(h);
        __nv_bfloat16 l = __float2bfloat16(vals[j] - hf);
        sp[base + k]       = h;    // hi in cols [0,256)
        sp[base + 256 + k] = l;    // lo in cols [256,512)
    }
    float s2 = v0.x*v0.x + v0.y*v0.y + v0.z*v0.z + v0.w*v0.w
             + v1.x*v1.x + v1.y*v1.y + v1.z*v1.z + v1.w*v1.w;
    #pragma unroll
    for (int off = 16; off; off >>= 1) s2 += __shfl_xor_sync(0xffffffffu, s2, off);
    if (lane == 0) {
        if (is_code) g_enorm2[warp] = s2; else g_znorm2[warp] = s2;
    }
}

// ---------------- HMMA GEMM (logical K=768) + fused top-2 argmin ----------------
// dot = zhi.ehi + zhi.elo + zlo.ehi  (residual zlo.elo ~ 2e-7, guarded)
// A physical chunks (128 k each): 0,1=zhi  2,3=zlo ; logical c -> A phys, B col:
//   c:      0    1    2    3    4    5
//   Aphys:  0    1    0    1    2    3
//   Bcol:   0  128  256  384    0  128
__device__ __constant__ int c_aphys[NCHUNK] = {0, 1, 0, 1, 2, 3};
__device__ __constant__ int c_bcol [NCHUNK] = {0, 128, 256, 384, 0, 128};

__global__ __launch_bounds__(256, 1)
void gemm_mma() {
    extern __shared__ char smem[];
    const uint32_t s_a = smem_u32(smem);
    const uint32_t s_b = s_a + A_BYTES;

    const int tid    = threadIdx.x;
    const int lane   = tid & 31;
    const int wid    = tid >> 5;
    const int warp_m = wid >> 1;
    const int warp_n = wid & 1;
    const int qbase  = blockIdx.x * 128;
    const int nb0    = blockIdx.y * 512;

    // ---- A strip (128 x 512 bf16 = [zhi|zlo]) via cp.async ----
    {
        const __nv_bfloat16* zp = g_zsplit;
        #pragma unroll
        for (int i = 0; i < 32; i++) {
            int u   = tid + i * 256;
            int row = u >> 6;
            int cu  = u & 63;
            cp16(s_a + (uint32_t)(row * A_ROW_U + cu) * 16,
                 zp + (size_t)(qbase + row) * KS + cu * 8);
        }
        cp_commit();
    }
    // ---- prefetch B chunk 0 (sub 0, logical c=0 -> ehi cols 0-127) ----
    {
        const __nv_bfloat16* ep = g_esplit;
        #pragma unroll
        for (int i = 0; i < 8; i++) {
            int u   = tid + i * 256;
            int row = u >> 4;
            int cu  = u & 15;
            cp16(s_b + (uint32_t)(row * B_ROW_U + cu) * 16,
                 ep + (size_t)(nb0 + row) * KS + cu * 8);
        }
        cp_commit();
    }

    float z2s[4];
    #pragma unroll
    for (int mf = 0; mf < 2; mf++)
        #pragma unroll
        for (int rh = 0; rh < 2; rh++)
            z2s[mf * 2 + rh] = g_znorm2[qbase + warp_m * 32 + mf * 16 + (lane >> 2) + rh * 8];

    float bestv[4], sec[4];
    int   besti[4];
    #pragma unroll
    for (int i = 0; i < 4; i++) { bestv[i] = 3.4e38f; sec[i] = 3.4e38f; besti[i] = 0; }

    const uint32_t a_base = s_a + (uint32_t)((warp_m * 32 + (lane & 15)) * A_ROW_U * 16
                          + (lane >> 4) * 16);
    const uint32_t b_row  = (uint32_t)(warp_n * 64 + (lane & 7) + ((lane >> 4) << 3));
    const uint32_t b_koff = (uint32_t)(((lane >> 3) & 1) * 16);

    float acc[2][8][4];
    const int TOT = 4 * NCHUNK;   // 24 chunk-steps

    #pragma unroll 1
    for (int sub = 0; sub < 4; sub++) {
        #pragma unroll
        for (int mf = 0; mf < 2; mf++)
            #pragma unroll
            for (int nf = 0; nf < 8; nf++) {
                acc[mf][nf][0] = 0.f; acc[mf][nf][1] = 0.f;
                acc[mf][nf][2] = 0.f; acc[mf][nf][3] = 0.f;
            }

        #pragma unroll 1
        for (int c = 0; c < NCHUNK; c++) {
            int g = sub * NCHUNK + c;
            if (g + 1 < TOT) {
                int ns = (g + 1) / NCHUNK, nc = (g + 1) % NCHUNK;
                uint32_t bdst = s_b + (uint32_t)(((g + 1) & 1) * B_BYTES);
                int bcol = c_bcol[nc];
                const __nv_bfloat16* ep = g_esplit;
                #pragma unroll
                for (int i = 0; i < 8; i++) {
                    int u   = tid + i * 256;
                    int row = u >> 4;
                    int cu  = u & 15;
                    cp16(bdst + (uint32_t)(row * B_ROW_U + cu) * 16,
                         ep + (size_t)(nb0 + ns * 128 + row) * KS + bcol + cu * 8);
                }
                cp_commit();
                cp_wait<1>();
            } else {
                cp_wait<0>();
            }
            __syncthreads();

            const uint32_t abase_c = a_base + (uint32_t)(c_aphys[c] * 256);
            const uint32_t bbuf    = s_b + (uint32_t)((g & 1) * B_BYTES);

            #pragma unroll
            for (int k16 = 0; k16 < 8; k16++) {
                uint32_t a0, a1, a2, a3, a4, a5, a6, a7;
                ldsm4(a0, a1, a2, a3, abase_c + k16 * 32);
                ldsm4(a4, a5, a6, a7, abase_c + 16 * A_ROW_U * 16 + k16 * 32);
                #pragma unroll
                for (int p = 0; p < 4; p++) {
                    uint32_t b0, b1, b2, b3;
                    ldsm4(b0, b1, b2, b3,
                          bbuf + (b_row + p * 16) * (B_ROW_U * 16) + b_koff + k16 * 32);
                    mma16816(acc[0][2 * p + 0], a0, a1, a2, a3, b0, b1);
                    mma16816(acc[0][2 * p + 1], a0, a1, a2, a3, b2, b3);
                    mma16816(acc[1][2 * p + 0], a4, a5, a6, a7, b0, b1);
                    mma16816(acc[1][2 * p + 1], a4, a5, a6, a7, b2, b3);
                }
            }
            __syncthreads();
        }

        // epilogue: fold this sub-tile's 128 codes into per-thread top-2
        int ncb = nb0 + sub * 128 + warp_n * 64 + 2 * (lane & 3);
        #pragma unroll
        for (int nf = 0; nf < 8; nf++) {
            float2 e2 = *(const float2*)&g_enorm2[ncb + nf * 8];
            #pragma unroll
            for (int mf = 0; mf < 2; mf++)
                #pragma unroll
                for (int rh = 0; rh < 2; rh++) {
                    int slot = mf * 2 + rh;
                    float d0 = acc[mf][nf][rh * 2 + 0];
                    float d1 = acc[mf][nf][rh * 2 + 1];
                    float k0 = z2s[slot] + e2.x - 2.0f * d0;
                    float k1 = z2s[slot] + e2.y - 2.0f * d1;
                    int   i0 = ncb + nf * 8;
                    if (k0 < bestv[slot]) { sec[slot] = bestv[slot]; bestv[slot] = k0; besti[slot] = i0; }
                    else if (k0 < sec[slot]) sec[slot] = k0;
                    if (k1 < bestv[slot]) { sec[slot] = bestv[slot]; bestv[slot] = k1; besti[slot] = i0 + 1; }
                    else if (k1 < sec[slot]) sec[slot] = k1;
                }
        }
    }

    // ---- block reduction: 8 contributors per row ----
    __syncthreads();
    float* rv = (float*)(smem + A_BYTES);
    int*   ri = (int*)  (smem + A_BYTES + 128 * 8 * 4);
    float* r2 = (float*)(smem + A_BYTES + 128 * 8 * 8);
    int contrib = (lane & 3) * 2 + warp_n;
    #pragma unroll
    for (int mf = 0; mf < 2; mf++)
        #pragma unroll
        for (int rh = 0; rh < 2; rh++) {
            int slot = mf * 2 + rh;
            int row  = warp_m * 32 + mf * 16 + (lane >> 2) + rh * 8;
            rv[row * 8 + contrib] = bestv[slot];
            ri[row * 8 + contrib] = besti[slot];
            r2[row * 8 + contrib] = sec[slot];
        }
    __syncthreads();
    if (tid < 128) {
        float b1 = 3.4e38f, b2 = 3.4e38f;
        int   i1 = 0x7fffffff;
        #pragma unroll
        for (int c = 0; c < 8; c++) {
            float bv = rv[tid * 8 + c];
            float sv = r2[tid * 8 + c];
            int   iv = ri[tid * 8 + c];
            if (bv < b1 || (bv == b1 && iv < i1)) {
                b2 = fminf(b2, fminf(b1, sv));
                b1 = bv; i1 = iv;
            } else {
                b2 = fminf(b2, fminf(bv, sv));
            }
        }
        int o = blockIdx.y * NQ + qbase + tid;
        g_part_best[o] = b1;
        g_part_2nd [o] = b2;
        g_part_idx [o] = i1;
    }
}

// ---------------- merge N-strips, flag ambiguous rows ----------------
__global__ void select_best() {
    int r = blockIdx.x * 256 + threadIdx.x;
    if (r >= NQ) return;
    float b1 = 3.4e38f, b2 = 3.4e38f;
    int   i1 = 0x7fffffff;
    #pragma unroll
    for (int c = 0; c < NSTRIP; c++) {
        float bv = g_part_best[c * NQ + r];
        float sv = g_part_2nd [c * NQ + r];
        int   iv = g_part_idx [c * NQ + r];
        if (bv < b1 || (bv == b1 && iv < i1)) {
            b2 = fminf(b2, fminf(b1, sv));
            b1 = bv; i1 = iv;
        } else {
            b2 = fminf(b2, fminf(bv, sv));
        }
    }
    g_idx[r]  = i1;
    g_flag[r] = (b2 - b1) < 3e-5f;
}

// ---------------- exact fp32 rescan for flagged rows (rare) ----------------
__global__ void exact_fix() {
    int row = blockIdx.x;
    if (!g_flag[row]) return;
    __shared__ float sv[256];
    __shared__ int   si[256];
    int tid = threadIdx.x;
    float z2 = g_znorm2[row];
    const float* zr = &g_znorm[(size_t)row * DIM];
    float bv = 3.4e38f; int bi = 0x7fffffff;
    for (int n = tid; n < NE; n += 256) {
        const float* er = &g_enorm[(size_t)n * DIM];
        float dot = 0.f;
        #pragma unroll 8
        for (int d = 0; d < DIM; d++) dot = fmaf(zr[d], er[d], dot);
        float key = z2 + g_enorm2[n] - 2.0f * dot;
        if (key < bv || (key == bv && n < bi)) { bv = key; bi = n; }
    }
    sv[tid] = bv; si[tid] = bi;
    __syncthreads();
    for (int off = 128; off; off >>= 1) {
        if (tid < off) {
            float v = sv[tid + off]; int ix = si[tid + off];
            if (v < sv[tid] || (v == sv[tid] && ix < si[tid])) { sv[tid] = v; si[tid] = ix; }
        }
        __syncthreads();
    }
    if (tid == 0) g_idx[row] = si[0];
}

// ---------------- gather z_q, loss partials, index output ----------------
__global__ void gather_loss(float* __restrict__ zq_out, float* __restrict__ idxf_out,
                            int write_zq) {
    __shared__ float wsum[8];
    int tid = threadIdx.x;
    int lane = tid & 31;
    int w = tid >> 5;
    int row = blockIdx.x * 8 + w;

    int e = g_idx[row] & (NE - 1);
    const float4* ev = (const float4*)(g_enorm + (size_t)e * DIM);
    const float4* zv = (const float4*)(g_znorm + (size_t)row * DIM);
    float4 a0 = ev[lane], a1 = ev[lane + 32];
    float4 b0 = zv[lane], b1 = zv[lane + 32];

    if (write_zq) {
        float4* o = (float4*)(zq_out + (size_t)row * DIM);
        o[lane]      = a0;
        o[lane + 32] = a1;
    }
    float dx, s = 0.f;
    dx = a0.x - b0.x; s += dx * dx;  dx = a0.y - b0.y; s += dx * dx;
    dx = a0.z - b0.z; s += dx * dx;  dx = a0.w - b0.w; s += dx * dx;
    dx = a1.x - b1.x; s += dx * dx;  dx = a1.y - b1.y; s += dx * dx;
    dx = a1.z - b1.z; s += dx * dx;  dx = a1.w - b1.w; s += dx * dx;
    #pragma unroll
    for (int off = 16; off; off >>= 1) s += __shfl_xor_sync(0xffffffffu, s, off);
    if (lane == 0) {
        wsum[w] = s;
        if (idxf_out) idxf_out[row] = (float)e;
    }
    __syncthreads();
    if (tid == 0) {
        float t = 0.f;
        #pragma unroll
        for (int i = 0; i < 8; i++) t += wsum[i];
        g_partial[blockIdx.x] = t;
    }
}

__global__ void finalize_loss(float* __restrict__ loss_out) {
    __shared__ float sh[256];
    int tid = threadIdx.x;
    float s = 0.f;
    for (int i = tid; i < 1024; i += 256) s += g_partial[i];
    sh[tid] = s;
    __syncthreads();
    for (int off = 128; off; off >>= 1) {
        if (tid < off) sh[tid] += sh[tid + off];
        __syncthreads();
    }
    if (tid == 0 && loss_out) loss_out[0] = 1.25f * sh[0] / (float)ZQ_ELEMS;
}

// ---------------- launch (no __device__ symbols below!) ----------------
extern "C" void kernel_launch(void* const* d_in, const int* in_sizes, int n_in,
                              void* d_out, int out_size) {
    const float* z  = (const float*)d_in[0];
    const float* ew = (const float*)d_in[1];
    float* out = (float*)d_out;

    int   write_zq = 0;
    float* lossp = nullptr;
    float* idxf  = nullptr;
    if (out_size >= ZQ_ELEMS) {
        write_zq = 1;
        long R = (long)out_size - (long)ZQ_ELEMS;
        if (R >= (long)NQ + 1)      { lossp = out + ZQ_ELEMS; idxf = out + ZQ_ELEMS + 1; }
        else if (R == (long)NQ)     { idxf = out + ZQ_ELEMS; }
        else if (R >= 1)            { lossp = out + ZQ_ELEMS; }
    } else if (out_size == NQ) {
        idxf = out;
    } else if (out_size == 1) {
        lossp = out;
    }

    static int smem_set = 0;
    if (!smem_set) {
        cudaFuncSetAttribute(gemm_mma, cudaFuncAttributeMaxDynamicSharedMemorySize, SMEM_MM);
        smem_set = 1;
    }

    l2norm_rows<<<NE / 8, 256>>>(ew, NE, 1);
    l2norm_rows<<<NQ / 8, 256>>>(z, NQ, 0);
    dim3 grid(64, NSTRIP);
    gemm_mma<<<grid, 256, SMEM_MM>>>();
    select_best<<<NQ / 256, 256>>>();
    exact_fix<<<NQ, 256>>>();
    gather_loss<<<NQ / 8, 256>>>(out, idxf, write_zq);
    finalize_loss<<<1, 256>>>(lossp);
}